// round 6
// baseline (speedup 1.0000x reference)
#include <cuda_runtime.h>
#include <cuda_bf16.h>
#include <cstdint>
#include <math.h>

#define EMAX   250000
#define DEDGE  128
#define DTRI   64

// fp32 intermediates
static __device__ __align__(16) float g_R  [EMAX * DEDGE];
static __device__ __align__(16) float g_T  [EMAX * DTRI];
static __device__ __align__(16) float g_Z  [EMAX * DEDGE];
// bf16 hi/lo pre-split activations
static __device__ __align__(16) __nv_bfloat16 g_msth[EMAX * DEDGE];
static __device__ __align__(16) __nv_bfloat16 g_mstl[EMAX * DEDGE];
static __device__ __align__(16) __nv_bfloat16 g_rbfh[EMAX * 16];
static __device__ __align__(16) __nv_bfloat16 g_rbfl[EMAX * 16];
static __device__ __align__(16) __nv_bfloat16 g_M1h [EMAX * DEDGE];
static __device__ __align__(16) __nv_bfloat16 g_M1l [EMAX * DEDGE];
static __device__ __align__(16) __nv_bfloat16 g_Xh  [EMAX * DTRI];
static __device__ __align__(16) __nv_bfloat16 g_Xl  [EMAX * DTRI];
static __device__ __align__(16) __nv_bfloat16 g_Yh  [EMAX * DEDGE];
static __device__ __align__(16) __nv_bfloat16 g_Yl  [EMAX * DEDGE];
// bf16 hi/lo transposed weights [N][K]
static __device__ __align__(16) __nv_bfloat16 g_Wrbh [128 * 16],  g_Wrbl [128 * 16];
static __device__ __align__(16) __nv_bfloat16 g_Wmrh [128 * 128], g_Wmrl [128 * 128];
static __device__ __align__(16) __nv_bfloat16 g_Wmch [64 * 128],  g_Wmcl [64 * 128];
static __device__ __align__(16) __nv_bfloat16 g_Wdh  [128 * 64],  g_Wdl  [128 * 64];
static __device__ __align__(16) __nv_bfloat16 g_Wsth [128 * 128], g_Wstl [128 * 128];
static __device__ __align__(16) __nv_bfloat16 g_Wtsh [128 * 128], g_Wtsl [128 * 128];

#define INV_SQRT_2  0.70710678118654752440f
#define INV_SQRT_NB 0.35355339059327376220f

__device__ __forceinline__ float silu_f(float x) {
    return x / (1.0f + __expf(-x));
}
__device__ __forceinline__ uint32_t smem_u32(const void* p) {
    uint32_t a;
    asm("{ .reg .u64 t; cvta.to.shared.u64 t, %1; cvt.u32.u64 %0, t; }" : "=r"(a) : "l"(p));
    return a;
}
__device__ __forceinline__ void cp_async16(uint32_t dst, const void* src, bool v) {
    int sz = v ? 16 : 0;
    asm volatile("cp.async.cg.shared.global [%0], [%1], 16, %2;"
                 :: "r"(dst), "l"(src), "r"(sz));
}
#define CP_COMMIT() asm volatile("cp.async.commit_group;" ::: "memory")
template<int n> __device__ __forceinline__ void cp_wait() {
    asm volatile("cp.async.wait_group %0;" :: "n"(n) : "memory");
}
__device__ __forceinline__ void ldsm4(uint32_t addr, uint32_t& r0, uint32_t& r1,
                                      uint32_t& r2, uint32_t& r3) {
    asm volatile("ldmatrix.sync.aligned.m8n8.x4.shared.b16 {%0,%1,%2,%3}, [%4];"
                 : "=r"(r0), "=r"(r1), "=r"(r2), "=r"(r3) : "r"(addr));
}
__device__ __forceinline__ void mma_bf16(float* c, const uint32_t* a,
                                         uint32_t b0, uint32_t b1) {
    asm volatile(
        "mma.sync.aligned.m16n8k16.row.col.f32.bf16.bf16.f32 "
        "{%0,%1,%2,%3}, {%4,%5,%6,%7}, {%8,%9}, {%0,%1,%2,%3};"
        : "+f"(c[0]), "+f"(c[1]), "+f"(c[2]), "+f"(c[3])
        : "r"(a[0]), "r"(a[1]), "r"(a[2]), "r"(a[3]), "r"(b0), "r"(b1));
}
__device__ __forceinline__ void split1(float v, __nv_bfloat16& h, __nv_bfloat16& l) {
    h = __float2bfloat16(v);
    l = __float2bfloat16(v - __bfloat162float(h));
}
// XOR-swizzled byte offset for granule (row, q): 64B rows, 4x16B granules
__device__ __forceinline__ uint32_t swizb(int row, int q) {
    return (uint32_t)(row * 64 + (((q) ^ (row >> 1)) & 3) * 16);
}

// ---------------- setup split kernels ----------------
__global__ void split_rows(const float* __restrict__ src,
                           __nv_bfloat16* __restrict__ dh,
                           __nv_bfloat16* __restrict__ dl, int n2)
{
    int i = blockIdx.x * blockDim.x + threadIdx.x;
    if (i >= n2) return;
    float2 v = ((const float2*)src)[i];
    __nv_bfloat16 hx, lx, hy, ly;
    split1(v.x, hx, lx); split1(v.y, hy, ly);
    __nv_bfloat162 H; H.x = hx; H.y = hy;
    __nv_bfloat162 L; L.x = lx; L.y = ly;
    ((__nv_bfloat162*)dh)[i] = H;
    ((__nv_bfloat162*)dl)[i] = L;
}

// W[K][N] fp32 -> Wt[N][K] bf16 hi/lo
__global__ void split_w_t(const float* __restrict__ src,
                          __nv_bfloat16* __restrict__ dh,
                          __nv_bfloat16* __restrict__ dl, int K, int N)
{
    int i = blockIdx.x * blockDim.x + threadIdx.x;
    if (i >= K * N) return;
    int k = i / N, n = i % N;
    __nv_bfloat16 h, l;
    split1(src[i], h, l);
    dh[n * K + k] = h;
    dl[n * K + k] = l;
}

#define EPI_NONE 0
#define EPI_SILU 1
#define EPI_SILU_MUL 2
#define EPI_FINAL 3
#define OUT_F32 0
#define OUT_BF16HL 1

// C = epi(A @ Wt^T). A bf16 hi/lo [M][K], Wt bf16 hi/lo [N][K].
// CTA tile 256 x N, 8 warps (4M x 2N), warp tile 64 x N/2.
// bf16 split-3 mma, cp.async double-buffered K chunks of 32, XOR-swizzled smem.
template<int K, int N, int EPI, int OUT>
__global__ void __launch_bounds__(256)
gemm3(const __nv_bfloat16* __restrict__ Ah, const __nv_bfloat16* __restrict__ Al,
      const __nv_bfloat16* __restrict__ Bh, const __nv_bfloat16* __restrict__ Bl,
      const float* __restrict__ Rm, float* __restrict__ outf,
      __nv_bfloat16* __restrict__ oh, __nv_bfloat16* __restrict__ ol,
      const float* __restrict__ Zg, const int* __restrict__ swp, int M)
{
    constexpr int NT    = N / 16;          // n8-tiles per warp (warp covers N/2)
    constexpr int NPAIR = NT / 2;
    constexpr int NCH   = (K + 31) / 32;
    // byte offsets within a stage
    constexpr uint32_t OFF_AL = 256 * 64;              // 16384
    constexpr uint32_t OFF_BH = 2 * 256 * 64;          // 32768
    constexpr uint32_t OFF_BL = OFF_BH + N * 64;
    constexpr uint32_t SSZ    = OFF_BH + 2 * N * 64;   // stage bytes

    extern __shared__ __align__(16) char smu[];
    const uint32_t sbase = smem_u32(smu);

    const int tid  = threadIdx.x;
    const int warp = tid >> 5, lane = tid & 31;
    const int g = lane >> 2, t = lane & 3;
    const int warpM = warp & 3, warpN = warp >> 2;
    const int m0 = warpM * 64;
    const int n0 = warpN * (N / 2);
    const int blockRow = blockIdx.x * 256;

    const int lr  = lane & 7;
    const int rowA_base = m0 + lr + ((lane >> 3) & 1) * 8;
    const int hkA = lane >> 4;
    const int rowB_base = n0 + lr + (lane >> 4) * 8;
    const int hkB = (lane >> 3) & 1;

    float acc[4][NT][4];
    #pragma unroll
    for (int mt = 0; mt < 4; mt++)
        #pragma unroll
        for (int nt = 0; nt < NT; nt++)
            #pragma unroll
            for (int j = 0; j < 4; j++) acc[mt][nt][j] = 0.0f;

    auto load_chunk = [&](int kb, int stage) {
        const int k0 = kb * 32;
        const uint32_t sb = sbase + (uint32_t)stage * SSZ;
        #pragma unroll
        for (int j = 0; j < 4; j++) {                 // A: 1024 granules/array
            int gg = tid + j * 256;
            int row = gg >> 2, q = gg & 3;
            bool v = (blockRow + row < M) && (k0 + q * 8 < K);
            size_t so = (size_t)(blockRow + row) * K + k0 + q * 8;
            uint32_t d = sb + swizb(row, q);
            cp_async16(d, v ? (Ah + so) : Ah, v);
            cp_async16(d + OFF_AL, v ? (Al + so) : Al, v);
        }
        #pragma unroll
        for (int j = 0; j < (N * 4) / 256; j++) {     // B: N*4 granules/array
            int gg = tid + j * 256;
            int row = gg >> 2, q = gg & 3;
            bool v = (k0 + q * 8 < K);
            size_t so = (size_t)row * K + k0 + q * 8;
            uint32_t d = sb + OFF_BH + swizb(row, q);
            cp_async16(d, v ? (Bh + so) : Bh, v);
            cp_async16(d + (uint32_t)(N * 64), v ? (Bl + so) : Bl, v);
        }
        CP_COMMIT();
    };

    load_chunk(0, 0);

    for (int kb = 0; kb < NCH; kb++) {
        if (kb + 1 < NCH) {
            load_chunk(kb + 1, (kb + 1) & 1);
            cp_wait<1>();
        } else {
            cp_wait<0>();
        }
        __syncthreads();

        const uint32_t sb = sbase + (uint32_t)(kb & 1) * SSZ;
        #pragma unroll
        for (int ks = 0; ks < 2; ks++) {
            uint32_t ah[4][4], al[4][4];
            #pragma unroll
            for (int mt = 0; mt < 4; mt++) {
                uint32_t ea = swizb(rowA_base + mt * 16, 2 * ks + hkA);
                ldsm4(sb + ea,          ah[mt][0], ah[mt][1], ah[mt][2], ah[mt][3]);
                ldsm4(sb + OFF_AL + ea, al[mt][0], al[mt][1], al[mt][2], al[mt][3]);
            }
            #pragma unroll
            for (int p = 0; p < NPAIR; p++) {
                uint32_t eb = swizb(rowB_base + p * 16, 2 * ks + hkB);
                uint32_t bh0, bh1, bh2, bh3, bl0, bl1, bl2, bl3;
                ldsm4(sb + OFF_BH + eb, bh0, bh1, bh2, bh3);
                ldsm4(sb + OFF_BL + eb, bl0, bl1, bl2, bl3);
                #pragma unroll
                for (int mt = 0; mt < 4; mt++) {
                    float* c0 = acc[mt][2 * p];
                    float* c1 = acc[mt][2 * p + 1];
                    mma_bf16(c0, ah[mt], bh0, bh1);
                    mma_bf16(c0, ah[mt], bl0, bl1);
                    mma_bf16(c0, al[mt], bh0, bh1);
                    mma_bf16(c1, ah[mt], bh2, bh3);
                    mma_bf16(c1, ah[mt], bl2, bl3);
                    mma_bf16(c1, al[mt], bh2, bh3);
                }
            }
        }
        __syncthreads();
    }

    // ---- epilogue ----
    #pragma unroll
    for (int mt = 0; mt < 4; mt++) {
        #pragma unroll
        for (int half = 0; half < 2; half++) {
            int r = blockRow + m0 + mt * 16 + g + half * 8;
            if (r >= M) continue;
            int s = 0;
            if (EPI == EPI_FINAL) s = swp[r];
            #pragma unroll
            for (int nt = 0; nt < NT; nt++) {
                int cc = n0 + nt * 8 + 2 * t;
                float v0 = acc[mt][nt][half * 2 + 0];
                float v1 = acc[mt][nt][half * 2 + 1];
                if (EPI != EPI_NONE) { v0 = silu_f(v0); v1 = silu_f(v1); }
                if (EPI == EPI_SILU_MUL) {
                    float2 rm = *(const float2*)(Rm + (size_t)r * N + cc);
                    v0 *= rm.x; v1 *= rm.y;
                }
                if (EPI == EPI_FINAL) {
                    float2 z = *(const float2*)(Zg + (size_t)s * N + cc);
                    v0 = (v0 + z.x) * INV_SQRT_2;
                    v1 = (v1 + z.y) * INV_SQRT_2;
                }
                if (OUT == OUT_F32) {
                    float2 o; o.x = v0; o.y = v1;
                    *(float2*)(outf + (size_t)r * N + cc) = o;
                } else {
                    __nv_bfloat16 h0, l0, h1, l1;
                    split1(v0, h0, l0); split1(v1, h1, l1);
                    __nv_bfloat162 H; H.x = h0; H.y = h1;
                    __nv_bfloat162 L; L.x = l0; L.y = l1;
                    *(__nv_bfloat162*)(oh + (size_t)r * N + cc) = H;
                    *(__nv_bfloat162*)(ol + (size_t)r * N + cc) = L;
                }
            }
        }
    }
}

// Triplet gather: X[e][:] = INV_SQRT_NB * sum_nb T[b1[e,nb]][:] * (cbf[e,nb,:] @ W_cbf)
__global__ void __launch_bounds__(256)
triplet_kernel(const float* __restrict__ T, const float* __restrict__ cbf,
               const int* __restrict__ idx_s, const int* __restrict__ basis,
               const float* __restrict__ Wc,
               __nv_bfloat16* __restrict__ Xh, __nv_bfloat16* __restrict__ Xl, int E)
{
    __shared__ float cb[8][128];
    const int warp = threadIdx.x >> 5;
    const int lane = threadIdx.x & 31;

    float w0[16], w1[16];
    #pragma unroll
    for (int c = 0; c < 16; c++) {
        w0[c] = Wc[c * 64 + lane];
        w1[c] = Wc[c * 64 + 32 + lane];
    }

    const int gw = blockIdx.x * 8 + warp;
    const int nwarps = gridDim.x * 8;

    for (int e = gw; e < E; e += nwarps) {
        int s = idx_s[e];
        int b1v = 0;
        if (lane < 8) b1v = basis[s * 8 + lane];

        float4 v = *(const float4*)(cbf + (size_t)e * 128 + lane * 4);
        *(float4*)(&cb[warp][lane * 4]) = v;
        __syncwarp();

        int bidx[8];
        #pragma unroll
        for (int nb = 0; nb < 8; nb++)
            bidx[nb] = __shfl_sync(0xffffffffu, b1v, nb);

        float t0[8], t1[8];
        #pragma unroll
        for (int nb = 0; nb < 8; nb++) {
            t0[nb] = T[(size_t)bidx[nb] * 64 + lane];
            t1[nb] = T[(size_t)bidx[nb] * 64 + 32 + lane];
        }

        float acc0 = 0.f, acc1 = 0.f;
        #pragma unroll
        for (int nb = 0; nb < 8; nb++) {
            float d0 = 0.f, d1 = 0.f;
            #pragma unroll
            for (int c = 0; c < 16; c++) {
                float a = cb[warp][nb * 16 + c];
                d0 = fmaf(a, w0[c], d0);
                d1 = fmaf(a, w1[c], d1);
            }
            acc0 = fmaf(t0[nb], d0, acc0);
            acc1 = fmaf(t1[nb], d1, acc1);
        }
        float x0 = acc0 * INV_SQRT_NB;
        float x1 = acc1 * INV_SQRT_NB;
        __nv_bfloat16 h0, l0, h1, l1;
        split1(x0, h0, l0); split1(x1, h1, l1);
        Xh[(size_t)e * 64 + lane]      = h0;
        Xh[(size_t)e * 64 + 32 + lane] = h1;
        Xl[(size_t)e * 64 + lane]      = l0;
        Xl[(size_t)e * 64 + 32 + lane] = l1;
        __syncwarp();
    }
}

extern "C" void kernel_launch(void* const* d_in, const int* in_sizes, int n_in,
                              void* d_out, int out_size)
{
    const float* m_st     = (const float*)d_in[0];
    const float* rbf      = (const float*)d_in[1];
    const float* cbf      = (const float*)d_in[2];
    const int*   idx_s    = (const int*)d_in[3];
    const int*   idx_swap = (const int*)d_in[4];
    const int*   basis    = (const int*)d_in[5];
    const float* W_m_rbf  = (const float*)d_in[6];
    const float* W_rbf    = (const float*)d_in[7];
    const float* W_m_cbf  = (const float*)d_in[8];
    const float* W_cbf    = (const float*)d_in[9];
    const float* W_dir    = (const float*)d_in[10];
    const float* W_st     = (const float*)d_in[11];
    const float* W_ts     = (const float*)d_in[12];
    float* out = (float*)d_out;

    const int E = in_sizes[0] / DEDGE;

    float *pR, *pT, *pZ;
    __nv_bfloat16 *pmh, *pml, *prh, *prl, *pM1h, *pM1l, *pXh, *pXl, *pYh, *pYl;
    __nv_bfloat16 *wrbh, *wrbl, *wmrh, *wmrl, *wmch, *wmcl, *wdh, *wdl, *wsth, *wstl, *wtsh, *wtsl;
    cudaGetSymbolAddress((void**)&pR,   g_R);
    cudaGetSymbolAddress((void**)&pT,   g_T);
    cudaGetSymbolAddress((void**)&pZ,   g_Z);
    cudaGetSymbolAddress((void**)&pmh,  g_msth);  cudaGetSymbolAddress((void**)&pml, g_mstl);
    cudaGetSymbolAddress((void**)&prh,  g_rbfh);  cudaGetSymbolAddress((void**)&prl, g_rbfl);
    cudaGetSymbolAddress((void**)&pM1h, g_M1h);   cudaGetSymbolAddress((void**)&pM1l, g_M1l);
    cudaGetSymbolAddress((void**)&pXh,  g_Xh);    cudaGetSymbolAddress((void**)&pXl, g_Xl);
    cudaGetSymbolAddress((void**)&pYh,  g_Yh);    cudaGetSymbolAddress((void**)&pYl, g_Yl);
    cudaGetSymbolAddress((void**)&wrbh, g_Wrbh);  cudaGetSymbolAddress((void**)&wrbl, g_Wrbl);
    cudaGetSymbolAddress((void**)&wmrh, g_Wmrh);  cudaGetSymbolAddress((void**)&wmrl, g_Wmrl);
    cudaGetSymbolAddress((void**)&wmch, g_Wmch);  cudaGetSymbolAddress((void**)&wmcl, g_Wmcl);
    cudaGetSymbolAddress((void**)&wdh,  g_Wdh);   cudaGetSymbolAddress((void**)&wdl, g_Wdl);
    cudaGetSymbolAddress((void**)&wsth, g_Wsth);  cudaGetSymbolAddress((void**)&wstl, g_Wstl);
    cudaGetSymbolAddress((void**)&wtsh, g_Wtsh);  cudaGetSymbolAddress((void**)&wtsl, g_Wtsl);

    const int gB = (E + 255) / 256;

    // dynamic smem: 2 stages * (32768 + 2*N*64) bytes
    const int smem_n128 = 2 * (32768 + 2 * 128 * 64);  // 98304
    const int smem_n64  = 2 * (32768 + 2 * 64  * 64);  // 81920

    cudaFuncSetAttribute(gemm3<16, 128, EPI_NONE, OUT_F32>,
                         cudaFuncAttributeMaxDynamicSharedMemorySize, smem_n128);
    cudaFuncSetAttribute(gemm3<128, 128, EPI_SILU_MUL, OUT_BF16HL>,
                         cudaFuncAttributeMaxDynamicSharedMemorySize, smem_n128);
    cudaFuncSetAttribute(gemm3<128, 64, EPI_SILU, OUT_F32>,
                         cudaFuncAttributeMaxDynamicSharedMemorySize, smem_n64);
    cudaFuncSetAttribute(gemm3<64, 128, EPI_SILU, OUT_BF16HL>,
                         cudaFuncAttributeMaxDynamicSharedMemorySize, smem_n128);
    cudaFuncSetAttribute(gemm3<128, 128, EPI_SILU, OUT_F32>,
                         cudaFuncAttributeMaxDynamicSharedMemorySize, smem_n128);
    cudaFuncSetAttribute(gemm3<128, 128, EPI_FINAL, OUT_F32>,
                         cudaFuncAttributeMaxDynamicSharedMemorySize, smem_n128);

    // ---- setup: split weights (transposed) + activations ----
    split_w_t<<<(16 * 128 + 255) / 256, 256>>>(W_rbf,    wrbh, wrbl, 16, 128);
    split_w_t<<<(128 * 128 + 255) / 256, 256>>>(W_m_rbf, wmrh, wmrl, 128, 128);
    split_w_t<<<(128 * 64 + 255) / 256, 256>>>(W_m_cbf,  wmch, wmcl, 128, 64);
    split_w_t<<<(64 * 128 + 255) / 256, 256>>>(W_dir,    wdh, wdl, 64, 128);
    split_w_t<<<(128 * 128 + 255) / 256, 256>>>(W_st,    wsth, wstl, 128, 128);
    split_w_t<<<(128 * 128 + 255) / 256, 256>>>(W_ts,    wtsh, wtsl, 128, 128);
    split_rows<<<(E * 64 + 255) / 256, 256>>>(m_st, pmh, pml, E * 64);
    split_rows<<<(E * 8 + 255) / 256, 256>>>(rbf, prh, prl, E * 8);

    // K0: R = rbf @ W_rbf
    gemm3<16, 128, EPI_NONE, OUT_F32><<<gB, 256, smem_n128>>>(
        prh, prl, wrbh, wrbl, nullptr, pR, nullptr, nullptr, nullptr, nullptr, E);
    // K1: M1 = silu(m_st @ W_m_rbf) * R   -> bf16 hi/lo
    gemm3<128, 128, EPI_SILU_MUL, OUT_BF16HL><<<gB, 256, smem_n128>>>(
        pmh, pml, wmrh, wmrl, pR, nullptr, pM1h, pM1l, nullptr, nullptr, E);
    // K2: T = silu(M1 @ W_m_cbf)          -> fp32
    gemm3<128, 64, EPI_SILU, OUT_F32><<<gB, 256, smem_n64>>>(
        pM1h, pM1l, wmch, wmcl, nullptr, pT, nullptr, nullptr, nullptr, nullptr, E);
    // K3: triplet gather -> X bf16 hi/lo
    triplet_kernel<<<2048, 256>>>(pT, cbf, idx_s, basis, W_cbf, pXh, pXl, E);
    // K4: Y = silu(X @ W_dir)             -> bf16 hi/lo
    gemm3<64, 128, EPI_SILU, OUT_BF16HL><<<gB, 256, smem_n128>>>(
        pXh, pXl, wdh, wdl, nullptr, nullptr, pYh, pYl, nullptr, nullptr, E);
    // K5b: Z = silu(Y @ W_ts)             -> fp32 (must precede K5a)
    gemm3<128, 128, EPI_SILU, OUT_F32><<<gB, 256, smem_n128>>>(
        pYh, pYl, wtsh, wtsl, nullptr, pZ, nullptr, nullptr, nullptr, nullptr, E);
    // K5a (fused final): out = (silu(Y @ W_st) + Z[idx_swap]) * INV_SQRT_2
    gemm3<128, 128, EPI_FINAL, OUT_F32><<<gB, 256, smem_n128>>>(
        pYh, pYl, wsth, wstl, nullptr, out, nullptr, nullptr, pZ, idx_swap, E);
}

// round 7
// speedup vs baseline: 1.3722x; 1.3722x over previous
#include <cuda_runtime.h>
#include <cuda_bf16.h>
#include <cstdint>
#include <math.h>

#define EMAX   250000
#define DEDGE  128
#define DTRI   64

// fp32 intermediates
static __device__ __align__(16) float g_R  [EMAX * DEDGE];
static __device__ __align__(16) float g_T  [EMAX * DTRI];
static __device__ __align__(16) float g_Z  [EMAX * DEDGE];
// bf16 hi/lo pre-split activations
static __device__ __align__(16) __nv_bfloat16 g_msth[EMAX * DEDGE];
static __device__ __align__(16) __nv_bfloat16 g_mstl[EMAX * DEDGE];
static __device__ __align__(16) __nv_bfloat16 g_rbfh[EMAX * 16];
static __device__ __align__(16) __nv_bfloat16 g_rbfl[EMAX * 16];
static __device__ __align__(16) __nv_bfloat16 g_Xh  [EMAX * DTRI];
static __device__ __align__(16) __nv_bfloat16 g_Xl  [EMAX * DTRI];
static __device__ __align__(16) __nv_bfloat16 g_Yh  [EMAX * DEDGE];
static __device__ __align__(16) __nv_bfloat16 g_Yl  [EMAX * DEDGE];
// bf16 hi/lo transposed weights [N][K]
static __device__ __align__(16) __nv_bfloat16 g_Wrbh [128 * 16],  g_Wrbl [128 * 16];
static __device__ __align__(16) __nv_bfloat16 g_Wmrh [128 * 128], g_Wmrl [128 * 128];
static __device__ __align__(16) __nv_bfloat16 g_Wmch [64 * 128],  g_Wmcl [64 * 128];
static __device__ __align__(16) __nv_bfloat16 g_Wdh  [128 * 64],  g_Wdl  [128 * 64];
static __device__ __align__(16) __nv_bfloat16 g_Wsth [128 * 128], g_Wstl [128 * 128];
static __device__ __align__(16) __nv_bfloat16 g_Wtsh [128 * 128], g_Wtsl [128 * 128];

#define INV_SQRT_2  0.70710678118654752440f
#define INV_SQRT_NB 0.35355339059327376220f

__device__ __forceinline__ float silu_f(float x) {
    return x / (1.0f + __expf(-x));
}
__device__ __forceinline__ uint32_t smem_u32(const void* p) {
    uint32_t a;
    asm("{ .reg .u64 t; cvta.to.shared.u64 t, %1; cvt.u32.u64 %0, t; }" : "=r"(a) : "l"(p));
    return a;
}
__device__ __forceinline__ void cp_async16(uint32_t dst, const void* src, bool v) {
    int sz = v ? 16 : 0;
    asm volatile("cp.async.cg.shared.global [%0], [%1], 16, %2;"
                 :: "r"(dst), "l"(src), "r"(sz));
}
#define CP_COMMIT() asm volatile("cp.async.commit_group;" ::: "memory")
template<int n> __device__ __forceinline__ void cp_wait() {
    asm volatile("cp.async.wait_group %0;" :: "n"(n) : "memory");
}
__device__ __forceinline__ void ldsm4(uint32_t addr, uint32_t& r0, uint32_t& r1,
                                      uint32_t& r2, uint32_t& r3) {
    asm volatile("ldmatrix.sync.aligned.m8n8.x4.shared.b16 {%0,%1,%2,%3}, [%4];"
                 : "=r"(r0), "=r"(r1), "=r"(r2), "=r"(r3) : "r"(addr));
}
__device__ __forceinline__ void mma_bf16(float* c, const uint32_t* a,
                                         uint32_t b0, uint32_t b1) {
    asm volatile(
        "mma.sync.aligned.m16n8k16.row.col.f32.bf16.bf16.f32 "
        "{%0,%1,%2,%3}, {%4,%5,%6,%7}, {%8,%9}, {%0,%1,%2,%3};"
        : "+f"(c[0]), "+f"(c[1]), "+f"(c[2]), "+f"(c[3])
        : "r"(a[0]), "r"(a[1]), "r"(a[2]), "r"(a[3]), "r"(b0), "r"(b1));
}
__device__ __forceinline__ void split1(float v, __nv_bfloat16& h, __nv_bfloat16& l) {
    h = __float2bfloat16(v);
    l = __float2bfloat16(v - __bfloat162float(h));
}
__device__ __forceinline__ uint32_t pack2(__nv_bfloat16 a, __nv_bfloat16 b) {
    __nv_bfloat162 p; p.x = a; p.y = b;
    return *(uint32_t*)&p;
}

// ---------------- setup split kernels ----------------
__global__ void split_rows(const float* __restrict__ src,
                           __nv_bfloat16* __restrict__ dh,
                           __nv_bfloat16* __restrict__ dl, int n2)
{
    int i = blockIdx.x * blockDim.x + threadIdx.x;
    if (i >= n2) return;
    float2 v = ((const float2*)src)[i];
    __nv_bfloat16 hx, lx, hy, ly;
    split1(v.x, hx, lx); split1(v.y, hy, ly);
    ((uint32_t*)dh)[i] = pack2(hx, hy);
    ((uint32_t*)dl)[i] = pack2(lx, ly);
}

// W[K][N] fp32 -> Wt[N][K] bf16 hi/lo
__global__ void split_w_t(const float* __restrict__ src,
                          __nv_bfloat16* __restrict__ dh,
                          __nv_bfloat16* __restrict__ dl, int K, int N)
{
    int i = blockIdx.x * blockDim.x + threadIdx.x;
    if (i >= K * N) return;
    int k = i / N, n = i % N;
    __nv_bfloat16 h, l;
    split1(src[i], h, l);
    dh[n * K + k] = h;
    dl[n * K + k] = l;
}

#define EPI_NONE 0
#define EPI_SILU 1
#define EPI_FINAL 3

// ---------------- standalone GEMM (R5-proven tiling) ----------------
// C = epi(A @ Wt^T). A bf16 hi/lo [M][K], Wt bf16 hi/lo [N][K].
// 256 threads = 8 warps (4M x 2N), CTA tile 128 x N, warp tile 32 x N/2.
template<int K, int N, int EPI>
__global__ void __launch_bounds__(256, 2)
gemm_std(const __nv_bfloat16* __restrict__ Ah, const __nv_bfloat16* __restrict__ Al,
         const __nv_bfloat16* __restrict__ Bh, const __nv_bfloat16* __restrict__ Bl,
         float* __restrict__ outf,
         const float* __restrict__ Zg, const int* __restrict__ swp, int M)
{
    constexpr int NT    = N / 16;
    constexpr int NPAIR = NT / 2;
    constexpr int NCH   = (K + 31) / 32;
    constexpr int ST    = 40;
    constexpr uint32_t OFF_AL = 128 * ST * 2;      // bytes
    constexpr uint32_t OFF_BH = 2 * 128 * ST * 2;
    constexpr uint32_t OFF_BL = OFF_BH + N * ST * 2;
    constexpr uint32_t SSZ    = OFF_BH + 2 * N * ST * 2;

    extern __shared__ __align__(16) char smu[];
    const uint32_t sbase = smem_u32(smu);

    const int tid  = threadIdx.x;
    const int warp = tid >> 5, lane = tid & 31;
    const int g = lane >> 2, t = lane & 3;
    const int warpM = warp & 3, warpN = warp >> 2;
    const int m0 = warpM * 32;
    const int n0 = warpN * (N / 2);
    const int blockRow = blockIdx.x * 128;

    const int lr  = lane & 7;
    const int rowA_base = m0 + lr + ((lane >> 3) & 1) * 8;
    const int kA_off    = (lane >> 4) * 8;
    const int rowB_base = n0 + lr + (lane >> 4) * 8;
    const int kB_off    = ((lane >> 3) & 1) * 8;

    float acc[2][NT][4];
    #pragma unroll
    for (int mt = 0; mt < 2; mt++)
        #pragma unroll
        for (int nt = 0; nt < NT; nt++)
            #pragma unroll
            for (int j = 0; j < 4; j++) acc[mt][nt][j] = 0.0f;

    auto load_chunk = [&](int kb, int stage) {
        const int k0 = kb * 32;
        const uint32_t sb = sbase + (uint32_t)stage * SSZ;
        #pragma unroll
        for (int j = 0; j < 2; j++) {
            int gg = tid + j * 256;
            int row = gg >> 2, q = gg & 3;
            bool v = (blockRow + row < M) && (k0 + q * 8 < K);
            size_t so = (size_t)(blockRow + row) * K + k0 + q * 8;
            uint32_t d = sb + (uint32_t)(row * ST + q * 8) * 2;
            cp_async16(d, v ? (Ah + so) : Ah, v);
            cp_async16(d + OFF_AL, v ? (Al + so) : Al, v);
        }
        #pragma unroll
        for (int j = 0; j < (N * 4) / 256; j++) {
            int gg = tid + j * 256;
            int n = gg >> 2, q = gg & 3;
            bool v = (k0 + q * 8 < K);
            size_t so = (size_t)n * K + k0 + q * 8;
            uint32_t d = sb + OFF_BH + (uint32_t)(n * ST + q * 8) * 2;
            cp_async16(d, v ? (Bh + so) : Bh, v);
            cp_async16(d + (uint32_t)(N * ST * 2), v ? (Bl + so) : Bl, v);
        }
        CP_COMMIT();
    };

    load_chunk(0, 0);
    for (int kb = 0; kb < NCH; kb++) {
        if (kb + 1 < NCH) { load_chunk(kb + 1, (kb + 1) & 1); cp_wait<1>(); }
        else              { cp_wait<0>(); }
        __syncthreads();

        const uint32_t sb = sbase + (uint32_t)(kb & 1) * SSZ;
        #pragma unroll
        for (int ks = 0; ks < 2; ks++) {
            uint32_t ah[2][4], al[2][4];
            #pragma unroll
            for (int mt = 0; mt < 2; mt++) {
                uint32_t ea = (uint32_t)((rowA_base + mt * 16) * ST + ks * 16 + kA_off) * 2;
                ldsm4(sb + ea,          ah[mt][0], ah[mt][1], ah[mt][2], ah[mt][3]);
                ldsm4(sb + OFF_AL + ea, al[mt][0], al[mt][1], al[mt][2], al[mt][3]);
            }
            #pragma unroll
            for (int p = 0; p < NPAIR; p++) {
                uint32_t eb = (uint32_t)((rowB_base + p * 16) * ST + ks * 16 + kB_off) * 2;
                uint32_t bh0, bh1, bh2, bh3, bl0, bl1, bl2, bl3;
                ldsm4(sb + OFF_BH + eb, bh0, bh1, bh2, bh3);
                ldsm4(sb + OFF_BL + eb, bl0, bl1, bl2, bl3);
                #pragma unroll
                for (int mt = 0; mt < 2; mt++) {
                    float* c0 = acc[mt][2 * p];
                    float* c1 = acc[mt][2 * p + 1];
                    mma_bf16(c0, ah[mt], bh0, bh1);
                    mma_bf16(c0, ah[mt], bl0, bl1);
                    mma_bf16(c0, al[mt], bh0, bh1);
                    mma_bf16(c1, ah[mt], bh2, bh3);
                    mma_bf16(c1, ah[mt], bl2, bl3);
                    mma_bf16(c1, al[mt], bh2, bh3);
                }
            }
        }
        __syncthreads();
    }

    #pragma unroll
    for (int mt = 0; mt < 2; mt++) {
        #pragma unroll
        for (int half = 0; half < 2; half++) {
            int r = blockRow + m0 + mt * 16 + g + half * 8;
            if (r >= M) continue;
            int s = 0;
            if (EPI == EPI_FINAL) s = swp[r];
            #pragma unroll
            for (int nt = 0; nt < NT; nt++) {
                int cc = n0 + nt * 8 + 2 * t;
                float v0 = acc[mt][nt][half * 2 + 0];
                float v1 = acc[mt][nt][half * 2 + 1];
                if (EPI != EPI_NONE) { v0 = silu_f(v0); v1 = silu_f(v1); }
                if (EPI == EPI_FINAL) {
                    float2 z = *(const float2*)(Zg + (size_t)s * N + cc);
                    v0 = (v0 + z.x) * INV_SQRT_2;
                    v1 = (v1 + z.y) * INV_SQRT_2;
                }
                float2 o; o.x = v0; o.y = v1;
                *(float2*)(outf + (size_t)r * N + cc) = o;
            }
        }
    }
}

// ---------------- chained GEMM: phase1 (N1=128) -> smem -> phase2 (K2=128) ----------------
// Phase1: P = silu(A @ B1^T) [* Rm]; P stored bf16 hi/lo into smem slabs (and optionally gmem Y).
// Phase2: out2 = silu(P @ B2^T), A-fragments read from smem slabs.
template<int K1, int N2, bool HAS_RM, bool STORE_Y>
__global__ void __launch_bounds__(256, 2)
gemm_chain(const __nv_bfloat16* __restrict__ Ah, const __nv_bfloat16* __restrict__ Al,
           const __nv_bfloat16* __restrict__ B1h, const __nv_bfloat16* __restrict__ B1l,
           const float* __restrict__ Rm,
           const __nv_bfloat16* __restrict__ B2h, const __nv_bfloat16* __restrict__ B2l,
           float* __restrict__ out2,
           __nv_bfloat16* __restrict__ Yh, __nv_bfloat16* __restrict__ Yl, int M)
{
    constexpr int N1  = 128;
    constexpr int ST  = 40;
    constexpr int NCH1 = (K1 + 31) / 32;
    constexpr uint32_t OFF_AL = 128 * ST * 2;
    constexpr uint32_t OFF_BH = 2 * 128 * ST * 2;
    constexpr uint32_t SSZ    = OFF_BH + 2 * N1 * ST * 2;   // 40960
    constexpr uint32_t SLAB   = 128 * ST * 2 * 2;           // 20480 per k-chunk (hi+lo)
    constexpr uint32_t B2OFF  = 2 * SSZ;                    // 81920
    constexpr int NT2   = N2 / 16;
    constexpr int NPAIR2 = NT2 / 2;

    extern __shared__ __align__(16) char smu[];
    const uint32_t sbase = smem_u32(smu);

    const int tid  = threadIdx.x;
    const int warp = tid >> 5, lane = tid & 31;
    const int g = lane >> 2, t = lane & 3;
    const int warpM = warp & 3, warpN = warp >> 2;
    const int m0 = warpM * 32;
    const int n0 = warpN * 64;
    const int n0b = warpN * (N2 / 2);
    const int blockRow = blockIdx.x * 128;

    const int lr  = lane & 7;
    const int rowA_base = m0 + lr + ((lane >> 3) & 1) * 8;
    const int kA_off    = (lane >> 4) * 8;
    const int rowB_base = n0 + lr + (lane >> 4) * 8;
    const int rowB2_base = n0b + lr + (lane >> 4) * 8;
    const int kB_off    = ((lane >> 3) & 1) * 8;

    // ======== phase 1 ========
    {
        float acc[2][8][4];
        #pragma unroll
        for (int mt = 0; mt < 2; mt++)
            #pragma unroll
            for (int nt = 0; nt < 8; nt++)
                #pragma unroll
                for (int j = 0; j < 4; j++) acc[mt][nt][j] = 0.0f;

        auto load_chunk = [&](int kb, int stage) {
            const int k0 = kb * 32;
            const uint32_t sb = sbase + (uint32_t)stage * SSZ;
            #pragma unroll
            for (int j = 0; j < 2; j++) {
                int gg = tid + j * 256;
                int row = gg >> 2, q = gg & 3;
                bool v = (blockRow + row < M) && (k0 + q * 8 < K1);
                size_t so = (size_t)(blockRow + row) * K1 + k0 + q * 8;
                uint32_t d = sb + (uint32_t)(row * ST + q * 8) * 2;
                cp_async16(d, v ? (Ah + so) : Ah, v);
                cp_async16(d + OFF_AL, v ? (Al + so) : Al, v);
            }
            #pragma unroll
            for (int j = 0; j < 2; j++) {
                int gg = tid + j * 256;
                int n = gg >> 2, q = gg & 3;
                bool v = (k0 + q * 8 < K1);
                size_t so = (size_t)n * K1 + k0 + q * 8;
                uint32_t d = sb + OFF_BH + (uint32_t)(n * ST + q * 8) * 2;
                cp_async16(d, v ? (B1h + so) : B1h, v);
                cp_async16(d + (uint32_t)(N1 * ST * 2), v ? (B1l + so) : B1l, v);
            }
            CP_COMMIT();
        };

        load_chunk(0, 0);
        for (int kb = 0; kb < NCH1; kb++) {
            if (kb + 1 < NCH1) { load_chunk(kb + 1, (kb + 1) & 1); cp_wait<1>(); }
            else               { cp_wait<0>(); }
            __syncthreads();

            const uint32_t sb = sbase + (uint32_t)(kb & 1) * SSZ;
            #pragma unroll
            for (int ks = 0; ks < 2; ks++) {
                uint32_t ah[2][4], al[2][4];
                #pragma unroll
                for (int mt = 0; mt < 2; mt++) {
                    uint32_t ea = (uint32_t)((rowA_base + mt * 16) * ST + ks * 16 + kA_off) * 2;
                    ldsm4(sb + ea,          ah[mt][0], ah[mt][1], ah[mt][2], ah[mt][3]);
                    ldsm4(sb + OFF_AL + ea, al[mt][0], al[mt][1], al[mt][2], al[mt][3]);
                }
                #pragma unroll
                for (int p = 0; p < 4; p++) {
                    uint32_t eb = (uint32_t)((rowB_base + p * 16) * ST + ks * 16 + kB_off) * 2;
                    uint32_t bh0, bh1, bh2, bh3, bl0, bl1, bl2, bl3;
                    ldsm4(sb + OFF_BH + eb, bh0, bh1, bh2, bh3);
                    ldsm4(sb + OFF_BH + (uint32_t)(N1 * ST * 2) + eb, bl0, bl1, bl2, bl3);
                    #pragma unroll
                    for (int mt = 0; mt < 2; mt++) {
                        float* c0 = acc[mt][2 * p];
                        float* c1 = acc[mt][2 * p + 1];
                        mma_bf16(c0, ah[mt], bh0, bh1);
                        mma_bf16(c0, ah[mt], bl0, bl1);
                        mma_bf16(c0, al[mt], bh0, bh1);
                        mma_bf16(c1, ah[mt], bh2, bh3);
                        mma_bf16(c1, ah[mt], bl2, bl3);
                        mma_bf16(c1, al[mt], bh2, bh3);
                    }
                }
            }
            __syncthreads();
        }

        // epilogue 1: silu [*Rm], split, write to smem slabs (+ optional gmem Y)
        #pragma unroll
        for (int mt = 0; mt < 2; mt++) {
            #pragma unroll
            for (int half = 0; half < 2; half++) {
                int row  = m0 + mt * 16 + g + half * 8;    // local 0..127
                int grow = blockRow + row;
                #pragma unroll
                for (int nt = 0; nt < 8; nt++) {
                    int cc = n0 + nt * 8 + 2 * t;
                    float v0 = acc[mt][nt][half * 2 + 0];
                    float v1 = acc[mt][nt][half * 2 + 1];
                    v0 = silu_f(v0); v1 = silu_f(v1);
                    if (HAS_RM) {
                        if (grow < M) {
                            float2 rm = *(const float2*)(Rm + (size_t)grow * N1 + cc);
                            v0 *= rm.x; v1 *= rm.y;
                        }
                    }
                    if (grow >= M) { v0 = 0.0f; v1 = 0.0f; }
                    __nv_bfloat16 h0, l0, h1, l1;
                    split1(v0, h0, l0); split1(v1, h1, l1);
                    uint32_t H = pack2(h0, h1), L = pack2(l0, l1);
                    uint32_t chunk = (uint32_t)(cc >> 5);
                    uint32_t off = (uint32_t)(row * ST + (cc & 31)) * 2;
                    *(uint32_t*)(smu + chunk * SLAB + off)                = H;
                    *(uint32_t*)(smu + chunk * SLAB + OFF_AL + off)       = L;
                    if (STORE_Y && grow < M) {
                        *(uint32_t*)(Yh + (size_t)grow * N1 + cc) = H;
                        *(uint32_t*)(Yl + (size_t)grow * N1 + cc) = L;
                    }
                }
            }
        }
        __syncthreads();
    }

    // ======== phase 2: out2 = silu(P @ B2^T), K2 = 128 ========
    {
        float acc2[2][NT2][4];
        #pragma unroll
        for (int mt = 0; mt < 2; mt++)
            #pragma unroll
            for (int nt = 0; nt < NT2; nt++)
                #pragma unroll
                for (int j = 0; j < 4; j++) acc2[mt][nt][j] = 0.0f;

        const uint32_t b2base = sbase + B2OFF;

        for (int kb = 0; kb < 4; kb++) {
            // load B2 chunk (single-buffered)
            #pragma unroll
            for (int j = 0; j < (N2 * 4) / 256; j++) {
                int gg = tid + j * 256;
                int n = gg >> 2, q = gg & 3;
                size_t so = (size_t)n * 128 + kb * 32 + q * 8;
                uint32_t d = b2base + (uint32_t)(n * ST + q * 8) * 2;
                cp_async16(d, B2h + so, true);
                cp_async16(d + (uint32_t)(N2 * ST * 2), B2l + so, true);
            }
            CP_COMMIT();
            cp_wait<0>();
            __syncthreads();

            const uint32_t slab = sbase + (uint32_t)kb * SLAB;
            #pragma unroll
            for (int ks = 0; ks < 2; ks++) {
                uint32_t ah[2][4], al[2][4];
                #pragma unroll
                for (int mt = 0; mt < 2; mt++) {
                    uint32_t ea = (uint32_t)((rowA_base + mt * 16) * ST + ks * 16 + kA_off) * 2;
                    ldsm4(slab + ea,          ah[mt][0], ah[mt][1], ah[mt][2], ah[mt][3]);
                    ldsm4(slab + OFF_AL + ea, al[mt][0], al[mt][1], al[mt][2], al[mt][3]);
                }
                #pragma unroll
                for (int p = 0; p < NPAIR2; p++) {
                    uint32_t eb = (uint32_t)((rowB2_base + p * 16) * ST + ks * 16 + kB_off) * 2;
                    uint32_t bh0, bh1, bh2, bh3, bl0, bl1, bl2, bl3;
                    ldsm4(b2base + eb, bh0, bh1, bh2, bh3);
                    ldsm4(b2base + (uint32_t)(N2 * ST * 2) + eb, bl0, bl1, bl2, bl3);
                    #pragma unroll
                    for (int mt = 0; mt < 2; mt++) {
                        float* c0 = acc2[mt][2 * p];
                        float* c1 = acc2[mt][2 * p + 1];
                        mma_bf16(c0, ah[mt], bh0, bh1);
                        mma_bf16(c0, ah[mt], bl0, bl1);
                        mma_bf16(c0, al[mt], bh0, bh1);
                        mma_bf16(c1, ah[mt], bh2, bh3);
                        mma_bf16(c1, ah[mt], bl2, bl3);
                        mma_bf16(c1, al[mt], bh2, bh3);
                    }
                }
            }
            __syncthreads();
        }

        // epilogue 2: out2 = silu(acc2)
        #pragma unroll
        for (int mt = 0; mt < 2; mt++) {
            #pragma unroll
            for (int half = 0; half < 2; half++) {
                int r = blockRow + m0 + mt * 16 + g + half * 8;
                if (r >= M) continue;
                #pragma unroll
                for (int nt = 0; nt < NT2; nt++) {
                    int cc = n0b + nt * 8 + 2 * t;
                    float v0 = silu_f(acc2[mt][nt][half * 2 + 0]);
                    float v1 = silu_f(acc2[mt][nt][half * 2 + 1]);
                    float2 o; o.x = v0; o.y = v1;
                    *(float2*)(out2 + (size_t)r * N2 + cc) = o;
                }
            }
        }
    }
}

// Triplet gather: X[e][:] = INV_SQRT_NB * sum_nb T[b1[e,nb]][:] * (cbf[e,nb,:] @ W_cbf)
__global__ void __launch_bounds__(256)
triplet_kernel(const float* __restrict__ T, const float* __restrict__ cbf,
               const int* __restrict__ idx_s, const int* __restrict__ basis,
               const float* __restrict__ Wc,
               __nv_bfloat16* __restrict__ Xh, __nv_bfloat16* __restrict__ Xl, int E)
{
    __shared__ float cb[8][128];
    const int warp = threadIdx.x >> 5;
    const int lane = threadIdx.x & 31;

    float w0[16], w1[16];
    #pragma unroll
    for (int c = 0; c < 16; c++) {
        w0[c] = Wc[c * 64 + lane];
        w1[c] = Wc[c * 64 + 32 + lane];
    }

    const int gw = blockIdx.x * 8 + warp;
    const int nwarps = gridDim.x * 8;

    for (int e = gw; e < E; e += nwarps) {
        int s = idx_s[e];
        int b1v = 0;
        if (lane < 8) b1v = basis[s * 8 + lane];

        float4 v = *(const float4*)(cbf + (size_t)e * 128 + lane * 4);
        *(float4*)(&cb[warp][lane * 4]) = v;
        __syncwarp();

        int bidx[8];
        #pragma unroll
        for (int nb = 0; nb < 8; nb++)
            bidx[nb] = __shfl_sync(0xffffffffu, b1v, nb);

        float t0[8], t1[8];
        #pragma unroll
        for (int nb = 0; nb < 8; nb++) {
            t0[nb] = T[(size_t)bidx[nb] * 64 + lane];
            t1[nb] = T[(size_t)bidx[nb] * 64 + 32 + lane];
        }

        float acc0 = 0.f, acc1 = 0.f;
        #pragma unroll
        for (int nb = 0; nb < 8; nb++) {
            float d0 = 0.f, d1 = 0.f;
            #pragma unroll
            for (int c = 0; c < 16; c++) {
                float a = cb[warp][nb * 16 + c];
                d0 = fmaf(a, w0[c], d0);
                d1 = fmaf(a, w1[c], d1);
            }
            acc0 = fmaf(t0[nb], d0, acc0);
            acc1 = fmaf(t1[nb], d1, acc1);
        }
        float x0 = acc0 * INV_SQRT_NB;
        float x1 = acc1 * INV_SQRT_NB;
        __nv_bfloat16 h0, l0, h1, l1;
        split1(x0, h0, l0); split1(x1, h1, l1);
        Xh[(size_t)e * 64 + lane]      = h0;
        Xh[(size_t)e * 64 + 32 + lane] = h1;
        Xl[(size_t)e * 64 + lane]      = l0;
        Xl[(size_t)e * 64 + 32 + lane] = l1;
        __syncwarp();
    }
}

extern "C" void kernel_launch(void* const* d_in, const int* in_sizes, int n_in,
                              void* d_out, int out_size)
{
    const float* m_st     = (const float*)d_in[0];
    const float* rbf      = (const float*)d_in[1];
    const float* cbf      = (const float*)d_in[2];
    const int*   idx_s    = (const int*)d_in[3];
    const int*   idx_swap = (const int*)d_in[4];
    const int*   basis    = (const int*)d_in[5];
    const float* W_m_rbf  = (const float*)d_in[6];
    const float* W_rbf    = (const float*)d_in[7];
    const float* W_m_cbf  = (const float*)d_in[8];
    const float* W_cbf    = (const float*)d_in[9];
    const float* W_dir    = (const float*)d_in[10];
    const float* W_st     = (const float*)d_in[11];
    const float* W_ts     = (const float*)d_in[12];
    float* out = (float*)d_out;

    const int E = in_sizes[0] / DEDGE;

    float *pR, *pT, *pZ;
    __nv_bfloat16 *pmh, *pml, *prh, *prl, *pXh, *pXl, *pYh, *pYl;
    __nv_bfloat16 *wrbh, *wrbl, *wmrh, *wmrl, *wmch, *wmcl, *wdh, *wdl, *wsth, *wstl, *wtsh, *wtsl;
    cudaGetSymbolAddress((void**)&pR,   g_R);
    cudaGetSymbolAddress((void**)&pT,   g_T);
    cudaGetSymbolAddress((void**)&pZ,   g_Z);
    cudaGetSymbolAddress((void**)&pmh,  g_msth);  cudaGetSymbolAddress((void**)&pml, g_mstl);
    cudaGetSymbolAddress((void**)&prh,  g_rbfh);  cudaGetSymbolAddress((void**)&prl, g_rbfl);
    cudaGetSymbolAddress((void**)&pXh,  g_Xh);    cudaGetSymbolAddress((void**)&pXl, g_Xl);
    cudaGetSymbolAddress((void**)&pYh,  g_Yh);    cudaGetSymbolAddress((void**)&pYl, g_Yl);
    cudaGetSymbolAddress((void**)&wrbh, g_Wrbh);  cudaGetSymbolAddress((void**)&wrbl, g_Wrbl);
    cudaGetSymbolAddress((void**)&wmrh, g_Wmrh);  cudaGetSymbolAddress((void**)&wmrl, g_Wmrl);
    cudaGetSymbolAddress((void**)&wmch, g_Wmch);  cudaGetSymbolAddress((void**)&wmcl, g_Wmcl);
    cudaGetSymbolAddress((void**)&wdh,  g_Wdh);   cudaGetSymbolAddress((void**)&wdl, g_Wdl);
    cudaGetSymbolAddress((void**)&wsth, g_Wsth);  cudaGetSymbolAddress((void**)&wstl, g_Wstl);
    cudaGetSymbolAddress((void**)&wtsh, g_Wtsh);  cudaGetSymbolAddress((void**)&wtsl, g_Wtsl);

    const int gB = (E + 127) / 128;

    const int smem_std   = 2 * (2 * 128 * 40 + 2 * 128 * 40) * 2;  // 81920
    const int smem_f12   = 81920 + 2 * 64  * 40 * 2;               // 92160
    const int smem_f45   = 81920 + 2 * 128 * 40 * 2;               // 102400

    cudaFuncSetAttribute(gemm_std<16, 128, EPI_NONE>,
                         cudaFuncAttributeMaxDynamicSharedMemorySize, smem_std);
    cudaFuncSetAttribute(gemm_std<128, 128, EPI_FINAL>,
                         cudaFuncAttributeMaxDynamicSharedMemorySize, smem_std);
    cudaFuncSetAttribute(gemm_chain<128, 64, true, false>,
                         cudaFuncAttributeMaxDynamicSharedMemorySize, smem_f12);
    cudaFuncSetAttribute(gemm_chain<64, 128, false, true>,
                         cudaFuncAttributeMaxDynamicSharedMemorySize, smem_f45);

    // ---- setup: split weights (transposed) + activations ----
    split_w_t<<<(16 * 128 + 255) / 256, 256>>>(W_rbf,    wrbh, wrbl, 16, 128);
    split_w_t<<<(128 * 128 + 255) / 256, 256>>>(W_m_rbf, wmrh, wmrl, 128, 128);
    split_w_t<<<(128 * 64 + 255) / 256, 256>>>(W_m_cbf,  wmch, wmcl, 128, 64);
    split_w_t<<<(64 * 128 + 255) / 256, 256>>>(W_dir,    wdh, wdl, 64, 128);
    split_w_t<<<(128 * 128 + 255) / 256, 256>>>(W_st,    wsth, wstl, 128, 128);
    split_w_t<<<(128 * 128 + 255) / 256, 256>>>(W_ts,    wtsh, wtsl, 128, 128);
    split_rows<<<(E * 64 + 255) / 256, 256>>>(m_st, pmh, pml, E * 64);
    split_rows<<<(E * 8 + 255) / 256, 256>>>(rbf, prh, prl, E * 8);

    // K0: R = rbf @ W_rbf
    gemm_std<16, 128, EPI_NONE><<<gB, 256, smem_std>>>(
        prh, prl, wrbh, wrbl, pR, nullptr, nullptr, E);
    // F12: M1 = silu(m_st @ W_m_rbf) * R  (smem)  ->  T = silu(M1 @ W_m_cbf)
    gemm_chain<128, 64, true, false><<<gB, 256, smem_f12>>>(
        pmh, pml, wmrh, wmrl, pR, wmch, wmcl, pT, nullptr, nullptr, E);
    // K3: triplet gather -> X bf16 hi/lo
    triplet_kernel<<<2048, 256>>>(pT, cbf, idx_s, basis, W_cbf, pXh, pXl, E);
    // F45: Y = silu(X @ W_dir) (smem + gmem)  ->  Z = silu(Y @ W_ts)
    gemm_chain<64, 128, false, true><<<gB, 256, smem_f45>>>(
        pXh, pXl, wdh, wdl, nullptr, wtsh, wtsl, pZ, pYh, pYl, E);
    // K5a (fused final): out = (silu(Y @ W_st) + Z[idx_swap]) * INV_SQRT_2
    gemm_std<128, 128, EPI_FINAL><<<gB, 256, smem_std>>>(
        pYh, pYl, wsth, wstl, out, pZ, idx_swap, E);
}